// round 1
// baseline (speedup 1.0000x reference)
#include <cuda_runtime.h>
#include <math.h>

// Problem constants (derived from reference):
//   image 2048x2048 -> DWT high (stride-2, 2x2, pad 0) -> 1024x1024
//   pad to 1449x1449 with pad_before=212 (both dims), center=724
//   out_h = out_w = 1448, N_ANGLES = 64
//   out[x*64 + t] = (sum_y bilinear(padded, rot_t(x,y))) / global_max
#define MDIM  2048
#define HN    1024
#define PDIM  1449
#define PB    212
#define OUTW  1448
#define NA    64
#define CENTERF 724.0f

__device__ float    g_pad[PDIM * PDIM];   // 8.4 MB scratch (padded DWT image)
__device__ unsigned g_maxkey;             // ordered-uint encoding of global max

// ---------------------------------------------------------------------------
// Kernel A: fused DWT high-pass + zero pad into g_pad; reset max key.
// high[i,j] = -0.1384*I[2i,2j] + 0.7243*I[2i,2j+1] - 0.6038*I[2i+1,2j] + 0.1601*I[2i+1,2j+1]
// ---------------------------------------------------------------------------
__global__ void dwt_pad_kernel(const float* __restrict__ img) {
    int idx = blockIdx.x * blockDim.x + threadIdx.x;
    if (idx == 0) g_maxkey = 0u;
    if (idx >= PDIM * PDIM) return;
    int py = idx / PDIM;
    int px = idx - py * PDIM;
    int iy = py - PB;
    int ix = px - PB;
    float v = 0.0f;
    if ((unsigned)iy < (unsigned)HN && (unsigned)ix < (unsigned)HN) {
        const float* r0 = img + (size_t)(2 * iy) * MDIM + 2 * ix;
        const float* r1 = r0 + MDIM;
        v = -0.1384f * r0[0] + 0.7243f * r0[1]
            - 0.6038f * r1[0] + 0.1601f * r1[1];
    }
    g_pad[idx] = v;
}

// ordered-uint encode: monotone map float -> uint so unsigned max == float max
__device__ __forceinline__ unsigned float_key(float f) {
    unsigned u = __float_as_uint(f);
    return (u & 0x80000000u) ? ~u : (u | 0x80000000u);
}

// ---------------------------------------------------------------------------
// Kernel B: rotate + column-sum for one (angle, 64-column tile) per block.
// blockDim = (64, 8): 64 output columns, 8 y-slices each, tree-reduced
// (deterministic). Writes UNNORMALIZED values to out[x*64 + t] and
// contributes to the global max via one atomicMax per warp.
// ---------------------------------------------------------------------------
__global__ void __launch_bounds__(512) rotsum_kernel(float* __restrict__ out) {
    const int t  = blockIdx.y;
    const int tx = threadIdx.x;
    const int ty = threadIdx.y;
    const int x  = blockIdx.x * 64 + tx;

    const float ang = (float)t;
    const float c = cosf(ang);
    const float s = sinf(ang);
    const float kx = CENTERF * (c + s - 1.0f);
    const float ky = CENTERF * (c - s - 1.0f);
    const float X = (float)x;

    float acc = 0.0f;
    #pragma unroll 4
    for (int y = ty; y < OUTW; y += 8) {
        const float Y = (float)y;
        float x_in = c * X + s * Y - kx;
        float y_in = -s * X + c * Y - ky;
        float x0f = floorf(x_in);
        float y0f = floorf(y_in);
        float dx = x_in - x0f;
        float dy = y_in - y0f;
        int x0 = (int)x0f % PDIM; if (x0 < 0) x0 += PDIM;
        int y0 = (int)y0f % PDIM; if (y0 < 0) y0 += PDIM;
        int x1 = x0 + 1; if (x1 == PDIM) x1 = 0;
        int y1 = y0 + 1; if (y1 == PDIM) y1 = 0;
        const float* __restrict__ row0 = g_pad + (size_t)y0 * PDIM;
        const float* __restrict__ row1 = g_pad + (size_t)y1 * PDIM;
        float v00 = __ldg(row0 + x0);
        float v01 = __ldg(row0 + x1);
        float v10 = __ldg(row1 + x0);
        float v11 = __ldg(row1 + x1);
        float top = v00 + dx * (v01 - v00);
        float bot = v10 + dx * (v11 - v10);
        acc += top + dy * (bot - top);
    }

    __shared__ float sm[8][64];
    sm[ty][tx] = acc;
    __syncthreads();
    #pragma unroll
    for (int off = 4; off > 0; off >>= 1) {
        if (ty < off) sm[ty][tx] += sm[ty + off][tx];
        __syncthreads();
    }

    if (ty == 0) {
        float v = sm[0][tx];
        if (x < OUTW) {
            out[(size_t)x * NA + t] = v;
        } else {
            v = -INFINITY;  // exclude padding columns from the max
        }
        unsigned key = float_key(v);
        #pragma unroll
        for (int o = 16; o > 0; o >>= 1) {
            unsigned other = __shfl_xor_sync(0xffffffffu, key, o);
            key = key > other ? key : other;
        }
        if ((tx & 31) == 0) atomicMax(&g_maxkey, key);
    }
}

// ---------------------------------------------------------------------------
// Kernel C: divide by decoded global max, in place.
// ---------------------------------------------------------------------------
__global__ void norm_kernel(float* __restrict__ out, int n) {
    int i = blockIdx.x * blockDim.x + threadIdx.x;
    unsigned key = g_maxkey;
    unsigned u = (key & 0x80000000u) ? (key ^ 0x80000000u) : ~key;
    float m = __uint_as_float(u);
    if (i < n) out[i] = out[i] / m;
}

// ---------------------------------------------------------------------------
extern "C" void kernel_launch(void* const* d_in, const int* in_sizes, int n_in,
                              void* d_out, int out_size) {
    const float* img = (const float*)d_in[0];
    float* out = (float*)d_out;

    dwt_pad_kernel<<<(PDIM * PDIM + 255) / 256, 256>>>(img);

    dim3 grid((OUTW + 63) / 64, NA);
    dim3 block(64, 8);
    rotsum_kernel<<<grid, block>>>(out);

    norm_kernel<<<(out_size + 255) / 256, 256>>>(out, out_size);
}

// round 2
// speedup vs baseline: 1.8345x; 1.8345x over previous
#include <cuda_runtime.h>
#include <math.h>

// image 2048x2048 -> DWT high (stride-2, 2x2) -> 1024x1024
// pad to 1449x1449 with pad_before=212, center=724
// out[x*64 + t] = (sum_y bilinear(padded, rot_t(x,y))) / global_max, x<1448
#define MDIM  2048
#define HN    1024
#define PDIM  1449
#define PB    212
#define OUTW  1448
#define NA    64
#define CENTERF 724.0f
// nonzero pixels: rows/cols in [212, 1235]. Sample contributes iff floor idx in [211,1235].
#define NZLO  211
#define NZSPAN 1024u   // (idx - 211) <= 1024

__device__ float    g_pad[PDIM * PDIM];
__device__ unsigned g_maxkey;

// ---------------------------------------------------------------------------
// Kernel A: fused DWT high-pass + zero pad (float2 reads); reset max key.
// ---------------------------------------------------------------------------
__global__ void dwt_pad_kernel(const float* __restrict__ img) {
    int idx = blockIdx.x * blockDim.x + threadIdx.x;
    if (idx == 0) g_maxkey = 0u;
    if (idx >= PDIM * PDIM) return;
    int py = idx / PDIM;
    int px = idx - py * PDIM;
    int iy = py - PB;
    int ix = px - PB;
    float v = 0.0f;
    if ((unsigned)iy < (unsigned)HN && (unsigned)ix < (unsigned)HN) {
        const float2* r0 = (const float2*)(img + (size_t)(2 * iy) * MDIM) + ix;
        const float2* r1 = (const float2*)((const float*)r0 + MDIM);
        float2 a = __ldg(r0);
        float2 b = __ldg(r1);
        v = -0.1384f * a.x + 0.7243f * a.y
            - 0.6038f * b.x + 0.1601f * b.y;
    }
    g_pad[idx] = v;
}

__device__ __forceinline__ unsigned float_key(float f) {
    unsigned u = __float_as_uint(f);
    return (u & 0x80000000u) ? ~u : (u | 0x80000000u);
}

// wrap an index known to lie in (-PDIM, 2*PDIM)
__device__ __forceinline__ int wrap_idx(int i) {
    if (i >= PDIM) i -= PDIM;
    if (i < 0)     i += PDIM;
    return i;
}

// Shared inner body: returns bilinear sample (0 if in zero region, loads skipped)
__device__ __forceinline__ float sample_pad(float x_in, float y_in) {
    float x0f = floorf(x_in);
    float y0f = floorf(y_in);
    int x0 = wrap_idx((int)x0f);
    int y0 = wrap_idx((int)y0f);
    bool nz = ((unsigned)(x0 - NZLO) <= NZSPAN) && ((unsigned)(y0 - NZLO) <= NZSPAN);
    float r = 0.0f;
    if (nz) {
        // nz guarantees x0 <= 1235, y0 <= 1235 -> no wrap for +1 neighbors
        float dx = x_in - x0f;
        float dy = y_in - y0f;
        const float* __restrict__ row0 = g_pad + (size_t)y0 * PDIM + x0;
        const float* __restrict__ row1 = row0 + PDIM;
        float v00 = __ldg(row0);
        float v01 = __ldg(row0 + 1);
        float v10 = __ldg(row1);
        float v11 = __ldg(row1 + 1);
        float top = v00 + dx * (v01 - v00);
        float bot = v10 + dx * (v11 - v10);
        r = top + dy * (bot - top);
    }
    return r;
}

// ---------------------------------------------------------------------------
// Variant A: |s| <= |c|  — lanes along X (rows change by s per lane: few rows).
// block (64, 8): 64 output columns, 8 y-slices, shared tree-reduce.
// ---------------------------------------------------------------------------
__global__ void __launch_bounds__(512) rotsumA_kernel(float* __restrict__ out) {
    const int t = blockIdx.y;
    const float ang = (float)t;
    const float c = cosf(ang);
    const float s = sinf(ang);
    if (fabsf(s) > fabsf(c)) return;   // variant B owns this angle

    const int tx = threadIdx.x;
    const int ty = threadIdx.y;
    const int x  = blockIdx.x * 64 + tx;

    const float kx = CENTERF * (c + s - 1.0f);
    const float ky = CENTERF * (c - s - 1.0f);
    const float X = (float)x;
    const float cxk = fmaf(c, X, -kx);   // x_in = s*Y + cxk
    const float syk = fmaf(-s, X, -ky);  // y_in = c*Y + syk

    float acc = 0.0f;
    #pragma unroll 4
    for (int y = ty; y < OUTW; y += 8) {
        const float Y = (float)y;
        acc += sample_pad(fmaf(s, Y, cxk), fmaf(c, Y, syk));
    }

    __shared__ float sm[8][64];
    sm[ty][tx] = acc;
    __syncthreads();
    #pragma unroll
    for (int off = 4; off > 0; off >>= 1) {
        if (ty < off) sm[ty][tx] += sm[ty + off][tx];
        __syncthreads();
    }

    if (ty == 0) {
        float v = sm[0][tx];
        if (x < OUTW) {
            out[(size_t)x * NA + t] = v;
        } else {
            v = -INFINITY;
        }
        unsigned key = float_key(v);
        #pragma unroll
        for (int o = 16; o > 0; o >>= 1) {
            unsigned other = __shfl_xor_sync(0xffffffffu, key, o);
            key = key > other ? key : other;
        }
        if ((tx & 31) == 0) atomicMax(&g_maxkey, key);
    }
}

// ---------------------------------------------------------------------------
// Variant B: |s| > |c|  — lanes along Y (rows change by c per lane: few rows).
// block 512 = 16 warps; each warp owns one output column x, warp-reduces.
// ---------------------------------------------------------------------------
__global__ void __launch_bounds__(512) rotsumB_kernel(float* __restrict__ out) {
    const int t = blockIdx.y;
    const float ang = (float)t;
    const float c = cosf(ang);
    const float s = sinf(ang);
    if (fabsf(s) <= fabsf(c)) return;  // variant A owns this angle

    const int w    = threadIdx.x >> 5;
    const int lane = threadIdx.x & 31;
    const int x    = blockIdx.x * 16 + w;
    if (x >= OUTW) return;             // warp-uniform

    const float kx = CENTERF * (c + s - 1.0f);
    const float ky = CENTERF * (c - s - 1.0f);
    const float X = (float)x;
    const float cxk = fmaf(c, X, -kx);
    const float syk = fmaf(-s, X, -ky);

    float acc = 0.0f;
    #pragma unroll 4
    for (int y = lane; y < OUTW; y += 32) {
        const float Y = (float)y;
        acc += sample_pad(fmaf(s, Y, cxk), fmaf(c, Y, syk));
    }

    #pragma unroll
    for (int o = 16; o > 0; o >>= 1)
        acc += __shfl_xor_sync(0xffffffffu, acc, o);

    if (lane == 0) {
        out[(size_t)x * NA + t] = acc;
        atomicMax(&g_maxkey, float_key(acc));
    }
}

// ---------------------------------------------------------------------------
__global__ void norm_kernel(float* __restrict__ out, int n) {
    int i = blockIdx.x * blockDim.x + threadIdx.x;
    unsigned key = g_maxkey;
    unsigned u = (key & 0x80000000u) ? (key ^ 0x80000000u) : ~key;
    float m = __uint_as_float(u);
    if (i < n) out[i] = out[i] / m;
}

// ---------------------------------------------------------------------------
extern "C" void kernel_launch(void* const* d_in, const int* in_sizes, int n_in,
                              void* d_out, int out_size) {
    const float* img = (const float*)d_in[0];
    float* out = (float*)d_out;

    dwt_pad_kernel<<<(PDIM * PDIM + 255) / 256, 256>>>(img);

    dim3 gridA((OUTW + 63) / 64, NA);
    rotsumA_kernel<<<gridA, dim3(64, 8)>>>(out);

    dim3 gridB((OUTW + 15) / 16, NA);
    rotsumB_kernel<<<gridB, 512>>>(out);

    norm_kernel<<<(out_size + 255) / 256, 256>>>(out, out_size);
}

// round 3
// speedup vs baseline: 2.4625x; 1.3424x over previous
#include <cuda_runtime.h>
#include <math.h>

// image 2048x2048 -> DWT high (stride-2, 2x2) -> 1024x1024
// pad to 1449x1449 with pad_before=212, center=724
// out[x*64 + t] = (sum_y bilinear(padded, rot_t(x,y))) / global_max, x<1448
#define MDIM  2048
#define HN    1024
#define PDIM  1449
#define PB    212
#define OUTW  1448
#define NA    64
#define CENTERF 724.0f
// nonzero pixels: rows/cols in [212, 1235]. Sample contributes iff floor idx in [211,1235].
#define NZLO  211
#define NZSPAN 1024u

__device__ float    g_pad[PDIM * PDIM];
__device__ unsigned g_maxkey;

// ---------------------------------------------------------------------------
// Kernel A: fused DWT high-pass + zero pad (float2 reads); reset max key.
// ---------------------------------------------------------------------------
__global__ void dwt_pad_kernel(const float* __restrict__ img) {
    int idx = blockIdx.x * blockDim.x + threadIdx.x;
    if (idx == 0) g_maxkey = 0u;
    if (idx >= PDIM * PDIM) return;
    int py = idx / PDIM;
    int px = idx - py * PDIM;
    int iy = py - PB;
    int ix = px - PB;
    float v = 0.0f;
    if ((unsigned)iy < (unsigned)HN && (unsigned)ix < (unsigned)HN) {
        const float2* r0 = (const float2*)(img + (size_t)(2 * iy) * MDIM) + ix;
        const float2* r1 = (const float2*)((const float*)r0 + MDIM);
        float2 a = __ldg(r0);
        float2 b = __ldg(r1);
        v = -0.1384f * a.x + 0.7243f * a.y
            - 0.6038f * b.x + 0.1601f * b.y;
    }
    g_pad[idx] = v;
}

__device__ __forceinline__ unsigned float_key(float f) {
    unsigned u = __float_as_uint(f);
    return (u & 0x80000000u) ? ~u : (u | 0x80000000u);
}

// wrap an index known to lie in (-PDIM, 2*PDIM)
__device__ __forceinline__ int wrap_idx(int i) {
    if (i >= PDIM) i -= PDIM;
    if (i < 0)     i += PDIM;
    return i;
}

// bilinear sample; loads skipped (predicated) when footprint is all-zero pad
__device__ __forceinline__ float sample_pad(float x_in, float y_in) {
    float x0f = floorf(x_in);
    float y0f = floorf(y_in);
    int x0 = wrap_idx((int)x0f);
    int y0 = wrap_idx((int)y0f);
    bool nz = ((unsigned)(x0 - NZLO) <= NZSPAN) && ((unsigned)(y0 - NZLO) <= NZSPAN);
    float r = 0.0f;
    if (nz) {
        // nz guarantees x0 <= 1235, y0 <= 1235 -> no wrap for +1 neighbors
        float dx = x_in - x0f;
        float dy = y_in - y0f;
        const float* __restrict__ row0 = g_pad + (size_t)y0 * PDIM + x0;
        const float* __restrict__ row1 = row0 + PDIM;
        float v00 = __ldg(row0);
        float v01 = __ldg(row0 + 1);
        float v10 = __ldg(row1);
        float v11 = __ldg(row1 + 1);
        float top = v00 + dx * (v01 - v00);
        float bot = v10 + dx * (v11 - v10);
        r = top + dy * (bot - top);
    }
    return r;
}

// ---------------------------------------------------------------------------
// Variant A: |s| <= |c|. Lane micro-tile 8(X) x 4(Y-phase); warp tiles 4(X) x 2(Y).
// Block 256 = 32 output columns x 8 Y-phases (stride 8 over 1448 rows).
// ---------------------------------------------------------------------------
__global__ void __launch_bounds__(256) rotsumA_kernel(float* __restrict__ out) {
    const int t = blockIdx.y;
    const float ang = (float)t;
    const float c = cosf(ang);
    const float s = sinf(ang);
    if (fabsf(s) > fabsf(c)) return;   // variant B owns this angle

    const int tid  = threadIdx.x;
    const int lane = tid & 31;
    const int w    = tid >> 5;
    const int lx = lane & 7;           // 8 lanes along X
    const int ly = lane >> 3;          // 4 lanes along Y-phase
    const int wx = w & 3;              // 4 warps along X
    const int wy = w >> 2;             // 2 warps along Y-phase
    const int col   = wx * 8 + lx;     // 0..31
    const int x     = blockIdx.x * 32 + col;
    const int phase = wy * 4 + ly;     // 0..7

    const float kx = CENTERF * (c + s - 1.0f);
    const float ky = CENTERF * (c - s - 1.0f);
    const float X = (float)x;
    const float cxk = fmaf(c, X, -kx);   // x_in = s*Y + cxk
    const float syk = fmaf(-s, X, -ky);  // y_in = c*Y + syk

    float acc = 0.0f;
    #pragma unroll 4
    for (int y = phase; y < OUTW; y += 8) {
        const float Y = (float)y;
        acc += sample_pad(fmaf(s, Y, cxk), fmaf(c, Y, syk));
    }

    __shared__ float sm[8][33];
    sm[phase][col] = acc;
    __syncthreads();

    if (tid < 32) {
        float v = sm[0][tid];
        #pragma unroll
        for (int p = 1; p < 8; p++) v += sm[p][tid];
        int xo = blockIdx.x * 32 + tid;
        float vm = v;
        if (xo < OUTW) out[(size_t)xo * NA + t] = v; else vm = -INFINITY;
        unsigned key = float_key(vm);
        #pragma unroll
        for (int o = 16; o > 0; o >>= 1) {
            unsigned other = __shfl_xor_sync(0xffffffffu, key, o);
            key = key > other ? key : other;
        }
        if (tid == 0) atomicMax(&g_maxkey, key);
    }
}

// ---------------------------------------------------------------------------
// Variant B: |s| > |c|. Lane micro-tile 4(X) x 8(Y-phase); 8 warps x 4 cols = 32 cols.
// Per-column reduction over the 8 Y-phase lanes via stride-4 shfl.
// ---------------------------------------------------------------------------
__global__ void __launch_bounds__(256) rotsumB_kernel(float* __restrict__ out) {
    const int t = blockIdx.y;
    const float ang = (float)t;
    const float c = cosf(ang);
    const float s = sinf(ang);
    if (fabsf(s) <= fabsf(c)) return;  // variant A owns this angle

    const int tid  = threadIdx.x;
    const int lane = tid & 31;
    const int w    = tid >> 5;
    const int lx  = lane & 3;          // 4 lanes along X
    const int lyp = lane >> 2;         // 8 lanes along Y-phase
    const int x   = blockIdx.x * 32 + w * 4 + lx;

    const float kx = CENTERF * (c + s - 1.0f);
    const float ky = CENTERF * (c - s - 1.0f);
    const float X = (float)x;
    const float cxk = fmaf(c, X, -kx);
    const float syk = fmaf(-s, X, -ky);

    float acc = 0.0f;
    #pragma unroll 4
    for (int y = lyp; y < OUTW; y += 8) {
        const float Y = (float)y;
        acc += sample_pad(fmaf(s, Y, cxk), fmaf(c, Y, syk));
    }

    // sum the 8 Y-phase lanes that share this column (bits 2..4 of lane id)
    #pragma unroll
    for (int o = 4; o < 32; o <<= 1)
        acc += __shfl_xor_sync(0xffffffffu, acc, o);

    if (lyp == 0 && x < OUTW) {
        out[(size_t)x * NA + t] = acc;
        atomicMax(&g_maxkey, float_key(acc));
    }
}

// ---------------------------------------------------------------------------
__global__ void norm_kernel(float* __restrict__ out, int n) {
    int i = blockIdx.x * blockDim.x + threadIdx.x;
    unsigned key = g_maxkey;
    unsigned u = (key & 0x80000000u) ? (key ^ 0x80000000u) : ~key;
    float m = __uint_as_float(u);
    if (i < n) out[i] = out[i] / m;
}

// ---------------------------------------------------------------------------
extern "C" void kernel_launch(void* const* d_in, const int* in_sizes, int n_in,
                              void* d_out, int out_size) {
    const float* img = (const float*)d_in[0];
    float* out = (float*)d_out;

    dwt_pad_kernel<<<(PDIM * PDIM + 255) / 256, 256>>>(img);

    dim3 grid((OUTW + 31) / 32, NA);
    rotsumA_kernel<<<grid, 256>>>(out);
    rotsumB_kernel<<<grid, 256>>>(out);

    norm_kernel<<<(out_size + 255) / 256, 256>>>(out, out_size);
}